// round 6
// baseline (speedup 1.0000x reference)
#include <cuda_runtime.h>
#include <math.h>
#include <stdint.h>

#define NB 64
#define MB 32
#define NM 2048         // node rows
#define FEATD 256
#define POSD 6
#define DD 262
#define DP 288          // padded feature dim (x4, 9 K-slabs of 32)
#define MSGD 128
#define NCLSD 7
#define G3 786
#define ABN 528         // AB GEMM N: A at cols 0..261, B at cols 264..525
#define ABLD 528
#define MGN 914
#define MGLD 916
#define GXN 786
#define GXLD 788

// ---------------- scratch (zero-initialized device globals) ----------------
__device__ float g_h  [NM*DP];     // fp32 h state (pad cols stay 0)
__device__ float g_hq [NM*DP];     // tf32-quantized h (GEMM A operand)
__device__ float g_AB [NM*ABLD];
__device__ float g_Wab[ABN*DP];    // quantized packed [W1a | 0 | W1b | 0]
__device__ float g_bab[ABLD];      // [b1 | 0]
__device__ float g_Wmg[MGN*DP];    // quantized packed [msg_w; gru_w_hh]
__device__ float g_bmg[MGLD];      // [msg_b | gru_b_hh | 0]
__device__ float g_Wih[G3*MSGD];   // quantized gru_w_ih
__device__ float g_mg [NM*MGLD];   // [msg | gh]
__device__ float g_att[NB*MB*MB];
__device__ float g_mv [NM*MSGD];   // quantized
__device__ float g_gx [NM*GXLD];
__device__ float g_w2p[264];       // padded link_w2
__device__ float g_zero[264];      // stays zero

__device__ __forceinline__ float sigmoidf(float x) {
    return 1.0f / (1.0f + expf(-x));
}
__device__ __forceinline__ uint32_t f2tf(float v) {
    uint32_t r; asm("cvt.rna.tf32.f32 %0, %1;" : "=r"(r) : "f"(v)); return r;
}
__device__ __forceinline__ float f2tff(float v) {
    return __uint_as_float(f2tf(v));
}
__device__ __forceinline__ void mma_tf32(float* c, const uint32_t* a, const uint32_t* b) {
    asm volatile(
        "mma.sync.aligned.m16n8k8.row.col.f32.tf32.tf32.f32 "
        "{%0,%1,%2,%3}, {%4,%5,%6,%7}, {%8,%9}, {%0,%1,%2,%3};\n"
        : "+f"(c[0]), "+f"(c[1]), "+f"(c[2]), "+f"(c[3])
        : "r"(a[0]), "r"(a[1]), "r"(a[2]), "r"(a[3]), "r"(b[0]), "r"(b[1]));
}

// ---------------- build h = [feat, pos] (fp32 + quantized copy) ----------------
__global__ void build_nf_kernel(const float* __restrict__ feat,
                                const float* __restrict__ pos) {
    int idx = blockIdx.x * blockDim.x + threadIdx.x;
    if (idx >= NM * DD) return;
    int row = idx / DD, c = idx % DD;
    float v = (c < FEATD) ? feat[row * FEATD + c] : pos[row * POSD + (c - FEATD)];
    g_h [row * DP + c] = v;
    g_hq[row * DP + c] = f2tff(v);
}

// ---------------- pack + pre-quantize weights ----------------
__global__ void pack_kernel(const float* __restrict__ link_w1,
                            const float* __restrict__ link_b1,
                            const float* __restrict__ link_w2,
                            const float* __restrict__ msg_w,
                            const float* __restrict__ msg_b,
                            const float* __restrict__ gru_w_ih,
                            const float* __restrict__ gru_w_hh,
                            const float* __restrict__ gru_b_hh) {
    int idx = blockIdx.x * blockDim.x + threadIdx.x;
    int stride = gridDim.x * blockDim.x;
    // Wab rows: 0..261 = W1a; 264..525 = W1b
    for (int i = idx; i < 524 * DD; i += stride) {
        int n = i / DD, k = i % DD;
        int dr = (n < DD) ? n : (n + 2);
        float v = (n < DD) ? link_w1[n * 524 + k] : link_w1[(n - DD) * 524 + DD + k];
        g_Wab[dr * DP + k] = f2tff(v);
    }
    for (int i = idx; i < MGN * DD; i += stride) {
        int n = i / DD, k = i % DD;
        float v = (n < MSGD) ? msg_w[n * DD + k] : gru_w_hh[(n - MSGD) * DD + k];
        g_Wmg[n * DP + k] = f2tff(v);
    }
    for (int i = idx; i < G3 * MSGD; i += stride) g_Wih[i] = f2tff(gru_w_ih[i]);
    for (int i = idx; i < DD; i += stride) {
        g_bab[i] = link_b1[i];
        g_w2p[i] = link_w2[i];
    }
    for (int i = idx; i < MGN; i += stride)
        g_bmg[i] = (i < MSGD) ? msg_b[i] : gru_b_hh[i - MSGD];
}

// ---------------- TF32 TC GEMM: C = A * W^T + bias ----------------
// A: 2048 x K (lda %4==0, values pre-quantized to tf32), W: N x K (quantized),
// C: 2048 x N. K % 32 == 0. Block 64x128, 8 warps, warp 32x32 m16n8k8.
#define BK 32
#define SLD 40   // u32 per smem row: 32 interleaved values + 8 pad (conflict-free LDS.64)
__global__ __launch_bounds__(256) void gemm_tc_kernel(
        const float* __restrict__ A, int lda,
        const float* __restrict__ W, int ldw,
        const float* __restrict__ bias,
        float* __restrict__ C, int ldc, int N, int K) {
    __shared__ uint32_t As[64 * SLD];
    __shared__ uint32_t Ws[128 * SLD];

    int tid = threadIdx.x;
    int warp = tid >> 5, lane = tid & 31;
    int gid = lane >> 2, tig = lane & 3;
    int wm = (warp >> 2) * 32;
    int wn = (warp & 3) * 32;
    int m0 = blockIdx.y * 64, n0 = blockIdx.x * 128;

    int arow = tid >> 2, akc = (tid & 3) * 8;   // A: 64 rows x 32k, 8 vals/thread
    int wrow = tid >> 1, wkc = (tid & 1) * 16;  // W: 128 rows x 32k, 16 vals/thread
    int wng = n0 + wrow;
    int wclamp = (wng < N) ? wng : (N - 1);
    const float4* ap = (const float4*)(A + (size_t)(m0 + arow) * lda + akc);
    const float4* wp = (const float4*)(W + (size_t)wclamp * ldw + wkc);

    float acc[2][4][4];
    #pragma unroll
    for (int i = 0; i < 2; i++)
        #pragma unroll
        for (int j = 0; j < 4; j++)
            #pragma unroll
            for (int q = 0; q < 4; q++) acc[i][j][q] = 0.0f;

    int nk = K / BK;
    float4 va0, va1, vw0, vw1, vw2, vw3;
    va0 = ap[0]; va1 = ap[1];
    vw0 = wp[0]; vw1 = wp[1]; vw2 = wp[2]; vw3 = wp[3];

    for (int it = 0; it < nk; it++) {
        __syncthreads();
        // interleaved stage: chunk[0..7] = [v0,v4,v1,v5,v2,v6,v3,v7]
        {
            uint32_t* ad = As + arow * SLD + akc;
            *(uint4*)(ad)     = make_uint4(__float_as_uint(va0.x), __float_as_uint(va1.x),
                                           __float_as_uint(va0.y), __float_as_uint(va1.y));
            *(uint4*)(ad + 4) = make_uint4(__float_as_uint(va0.z), __float_as_uint(va1.z),
                                           __float_as_uint(va0.w), __float_as_uint(va1.w));
            uint32_t* wd = Ws + wrow * SLD + wkc;
            *(uint4*)(wd)      = make_uint4(__float_as_uint(vw0.x), __float_as_uint(vw1.x),
                                            __float_as_uint(vw0.y), __float_as_uint(vw1.y));
            *(uint4*)(wd + 4)  = make_uint4(__float_as_uint(vw0.z), __float_as_uint(vw1.z),
                                            __float_as_uint(vw0.w), __float_as_uint(vw1.w));
            *(uint4*)(wd + 8)  = make_uint4(__float_as_uint(vw2.x), __float_as_uint(vw3.x),
                                            __float_as_uint(vw2.y), __float_as_uint(vw3.y));
            *(uint4*)(wd + 12) = make_uint4(__float_as_uint(vw2.z), __float_as_uint(vw3.z),
                                            __float_as_uint(vw2.w), __float_as_uint(vw3.w));
        }
        __syncthreads();

        if (it + 1 < nk) {
            int o = (it + 1) * 8;
            va0 = ap[o]; va1 = ap[o + 1];
            vw0 = wp[o]; vw1 = wp[o + 1]; vw2 = wp[o + 2]; vw3 = wp[o + 3];
        }

        #pragma unroll
        for (int ks = 0; ks < 4; ks++) {
            int kb = ks * 8 + tig * 2;
            uint32_t af[2][4], bf[4][2];
            #pragma unroll
            for (int mf = 0; mf < 2; mf++) {
                const uint32_t* pa = As + (wm + mf * 16 + gid) * SLD + kb;
                uint2 lo = *(const uint2*)pa;
                uint2 hi = *(const uint2*)(pa + 8 * SLD);
                af[mf][0] = lo.x; af[mf][2] = lo.y;
                af[mf][1] = hi.x; af[mf][3] = hi.y;
            }
            #pragma unroll
            for (int nf = 0; nf < 4; nf++) {
                const uint32_t* pb = Ws + (wn + nf * 8 + gid) * SLD + kb;
                uint2 v = *(const uint2*)pb;
                bf[nf][0] = v.x; bf[nf][1] = v.y;
            }
            #pragma unroll
            for (int mf = 0; mf < 2; mf++)
                #pragma unroll
                for (int nf = 0; nf < 4; nf++)
                    mma_tf32(acc[mf][nf], af[mf], bf[nf]);
        }
    }

    #pragma unroll
    for (int nf = 0; nf < 4; nf++) {
        int col = n0 + wn + nf * 8 + tig * 2;
        if (col >= N) continue;
        float2 bv = *(const float2*)(bias + col);
        #pragma unroll
        for (int mf = 0; mf < 2; mf++) {
            int r0 = m0 + wm + mf * 16 + gid;
            float2 v0 = make_float2(acc[mf][nf][0] + bv.x, acc[mf][nf][1] + bv.y);
            float2 v1 = make_float2(acc[mf][nf][2] + bv.x, acc[mf][nf][3] + bv.y);
            *(float2*)(C + (size_t)r0 * ldc + col) = v0;
            *(float2*)(C + (size_t)(r0 + 8) * ldc + col) = v1;
        }
    }
}

// ---------------- attention: warp per (b,n,w) pair, float4 loads ----------------
__global__ void att_kernel(const float* __restrict__ b2v,
                           const int* __restrict__ num_rec,
                           float* __restrict__ att_out) {
    int gw = (blockIdx.x * blockDim.x + threadIdx.x) >> 5;
    int lane = threadIdx.x & 31;
    if (gw >= NB * MB * MB) return;
    int b = gw >> 10, n = (gw >> 5) & 31, w = gw & 31;
    int nr = num_rec[b];
    bool valid = (n < nr) && (w < nr);

    const float4* ra = valid ? (const float4*)(g_AB + (size_t)(b * MB + n) * ABLD)
                             : (const float4*)g_bab;        // [b1 | 0]
    const float4* rb = valid ? (const float4*)(g_AB + (size_t)(b * MB + w) * ABLD + 264)
                             : (const float4*)g_zero;
    const float4* wv = (const float4*)g_w2p;

    float s = 0.0f;
    #pragma unroll 1
    for (int i = lane; i < 66; i += 32) {        // 264 floats (pad w2=0)
        float4 a = ra[i], bb = rb[i], ww = wv[i];
        s = fmaf(fmaxf(a.x + bb.x, 0.0f), ww.x, s);
        s = fmaf(fmaxf(a.y + bb.y, 0.0f), ww.y, s);
        s = fmaf(fmaxf(a.z + bb.z, 0.0f), ww.z, s);
        s = fmaf(fmaxf(a.w + bb.w, 0.0f), ww.w, s);
    }
    #pragma unroll
    for (int o = 16; o > 0; o >>= 1) s += __shfl_xor_sync(0xffffffffu, s, o);
    if (lane == 0) {
        float a = sigmoidf(s + b2v[0]);
        g_att[gw] = a;
        att_out[gw] = a;
    }
}

// ---------------- mv[b,n,k] = sum_{w<nr} att[b,n,w] * msg[b,w,k] (quantized out) ----------------
__global__ void mv_kernel(const int* __restrict__ num_rec) {
    int bn = blockIdx.x;
    int b = bn >> 5;
    int k = threadIdx.x;              // 0..127
    int nr = num_rec[b];
    const float* arow = g_att + (size_t)bn * MB;
    const float* mb = g_mg + (size_t)b * MB * MGLD;
    float s = 0.0f;
    for (int w = 0; w < nr; w++) s = fmaf(arow[w], mb[(size_t)w * MGLD + k], s);
    g_mv[(size_t)bn * MSGD + k] = f2tff(s);
}

// ---------------- GRU combine: h (fp32 + quantized), vmask, float2 ----------------
__global__ void gru_kernel(const int* __restrict__ num_rec) {
    int idx = blockIdx.x * blockDim.x + threadIdx.x;
    if (idx >= NM * 131) return;
    int row = idx / 131, d = (idx % 131) * 2;
    int b = row >> 5, m = row & 31;
    const float* gx = g_gx + (size_t)row * GXLD + d;
    const float* gh = g_mg + (size_t)row * MGLD + MSGD + d;
    float2 xr = *(const float2*)(gx);
    float2 xz = *(const float2*)(gx + 262);
    float2 xn = *(const float2*)(gx + 524);
    float2 hr = *(const float2*)(gh);
    float2 hz = *(const float2*)(gh + 262);
    float2 hn = *(const float2*)(gh + 524);
    float2 hv = *(const float2*)(g_h + (size_t)row * DP + d);
    float rx = sigmoidf(xr.x + hr.x), ry = sigmoidf(xr.y + hr.y);
    float zx = sigmoidf(xz.x + hz.x), zy = sigmoidf(xz.y + hz.y);
    float cx = tanhf(xn.x + rx * hn.x), cy = tanhf(xn.y + ry * hn.y);
    float ox = (1.0f - zx) * cx + zx * hv.x;
    float oy = (1.0f - zy) * cy + zy * hv.y;
    bool live = (m < num_rec[b]);
    ox = live ? ox : 0.0f;
    oy = live ? oy : 0.0f;
    *(float2*)(g_h  + (size_t)row * DP + d) = make_float2(ox, oy);
    *(float2*)(g_hq + (size_t)row * DP + d) = make_float2(f2tff(ox), f2tff(oy));
}

// ---------------- fused readout ----------------
#define SH_LD 266
#define ST_LD 133
__global__ void readout_kernel(const float* __restrict__ ro_w1,
                               const float* __restrict__ ro_b1,
                               const float* __restrict__ ro_w2,
                               const float* __restrict__ ro_b2,
                               const int* __restrict__ num_rec,
                               float* __restrict__ out) {
    extern __shared__ float s[];
    float* sh = s;                    // 32 x 266
    float* st = s + MB * SH_LD;       // 32 x 133
    int b = blockIdx.x;
    int tid = threadIdx.x;            // 0..511
    int lane = tid & 31, wid = tid >> 5;

    for (int i = tid; i < MB * 131; i += 512) {
        int r = i / 131, d = (i % 131) * 2;
        *(float2*)(sh + r * SH_LD + d) = *(const float2*)(g_h + (size_t)(b * MB + r) * DP + d);
    }
    __syncthreads();

    int r = lane;
    #pragma unroll 1
    for (int j = 0; j < 8; j++) {
        int k = wid * 8 + j;
        const float2* wrow = (const float2*)(ro_w1 + (size_t)k * DD);
        const float2* hrow = (const float2*)(sh + r * SH_LD);
        float acc = 0.0f;
        #pragma unroll 4
        for (int i = 0; i < DD / 2; i++) {
            float2 ww = __ldg(wrow + i);
            float2 hh = hrow[i];
            acc = fmaf(hh.x, ww.x, acc);
            acc = fmaf(hh.y, ww.y, acc);
        }
        st[r * ST_LD + k] = fmaxf(acc + ro_b1[k], 0.0f);
    }
    __syncthreads();

    if (tid < MB * NCLSD) {
        int rr = tid / NCLSD, c = tid % NCLSD;
        int nr = num_rec[b];
        float acc = ro_b2[c];
        #pragma unroll 4
        for (int k = 0; k < MSGD; k++)
            acc = fmaf(st[rr * ST_LD + k], __ldg(ro_w2 + (size_t)c * MSGD + k), acc);
        out[(size_t)(b * MB + rr) * NCLSD + c] = (rr < nr) ? acc : 0.0f;
    }
}

// ---------------- host launcher ----------------
static void launch_gemm(const float* A, int lda, const float* W, int ldw,
                        const float* bias, float* C, int ldc, int N, int K) {
    dim3 grid((N + 127) / 128, NM / 64);
    gemm_tc_kernel<<<grid, 256>>>(A, lda, W, ldw, bias, C, ldc, N, K);
}

extern "C" void kernel_launch(void* const* d_in, const int* in_sizes, int n_in,
                              void* d_out, int out_size) {
    const float* feat    = (const float*)d_in[0];
    const float* pos     = (const float*)d_in[1];
    const int*   num_rec = (const int*)  d_in[2];
    const float* link_w1 = (const float*)d_in[3];
    const float* link_b1 = (const float*)d_in[4];
    const float* link_w2 = (const float*)d_in[5];
    const float* link_b2 = (const float*)d_in[6];
    const float* msg_w   = (const float*)d_in[7];
    const float* msg_b   = (const float*)d_in[8];
    const float* gru_w_ih= (const float*)d_in[9];
    const float* gru_w_hh= (const float*)d_in[10];
    const float* gru_b_ih= (const float*)d_in[11];
    const float* gru_b_hh= (const float*)d_in[12];
    const float* ro_w1   = (const float*)d_in[13];
    const float* ro_b1   = (const float*)d_in[14];
    const float* ro_w2   = (const float*)d_in[15];
    const float* ro_b2   = (const float*)d_in[16];
    float* out = (float*)d_out;           // [pred (64*32*7) | attmat (64*32*32)]

    float *p_h, *p_hq, *p_AB, *p_Wab, *p_bab, *p_Wmg, *p_bmg, *p_Wih, *p_mg, *p_mv, *p_gx;
    cudaGetSymbolAddress((void**)&p_h,   g_h);
    cudaGetSymbolAddress((void**)&p_hq,  g_hq);
    cudaGetSymbolAddress((void**)&p_AB,  g_AB);
    cudaGetSymbolAddress((void**)&p_Wab, g_Wab);
    cudaGetSymbolAddress((void**)&p_bab, g_bab);
    cudaGetSymbolAddress((void**)&p_Wmg, g_Wmg);
    cudaGetSymbolAddress((void**)&p_bmg, g_bmg);
    cudaGetSymbolAddress((void**)&p_Wih, g_Wih);
    cudaGetSymbolAddress((void**)&p_mg,  g_mg);
    cudaGetSymbolAddress((void**)&p_mv,  g_mv);
    cudaGetSymbolAddress((void**)&p_gx,  g_gx);

    static const size_t RO_SMEM = (size_t)(MB * SH_LD + MB * ST_LD) * sizeof(float);
    cudaFuncSetAttribute(readout_kernel, cudaFuncAttributeMaxDynamicSharedMemorySize,
                         (int)RO_SMEM);

    // 1) h = [feat, pos] (+ quantized twin); pack + quantize weights
    build_nf_kernel<<<(NM * DD + 255) / 256, 256>>>(feat, pos);
    pack_kernel<<<296, 256>>>(link_w1, link_b1, link_w2, msg_w, msg_b,
                              gru_w_ih, gru_w_hh, gru_b_hh);

    // 2) edge MLP low-rank: AB = hq @ Wab^T + [b1|0]   (2048 x 528)
    launch_gemm(p_hq, DP, p_Wab, DP, p_bab, p_AB, ABLD, ABN, DP);

    // 3) attention
    {
        int threads = NB * MB * MB * 32;
        att_kernel<<<(threads + 255) / 256, 256>>>(link_b2, num_rec, out + NM * NCLSD);
    }

    // 4) two message-passing GRU rounds
    for (int round = 0; round < 2; round++) {
        launch_gemm(p_hq, DP, p_Wmg, DP, p_bmg, p_mg, MGLD, MGN, DP);    // [msg|gh]
        mv_kernel<<<NM, MSGD>>>(num_rec);
        launch_gemm(p_mv, MSGD, p_Wih, MSGD, gru_b_ih, p_gx, GXLD, GXN, MSGD);
        gru_kernel<<<(NM * 131 + 255) / 256, 256>>>(num_rec);
    }

    // 5) fused readout
    readout_kernel<<<NB, 512, RO_SMEM>>>(ro_w1, ro_b1, ro_w2, ro_b2, num_rec, out);

    (void)in_sizes; (void)n_in; (void)out_size;
}

// round 7
// speedup vs baseline: 1.4688x; 1.4688x over previous
#include <cuda_runtime.h>
#include <math.h>
#include <stdint.h>

#define NB 64
#define MB 32
#define NM 2048         // node rows
#define FEATD 256
#define POSD 6
#define DD 262
#define DP 288          // padded feature dim (x4, 9 K-slabs of 32)
#define MSGD 128
#define NCLSD 7
#define G3 786
#define ABN 528         // AB GEMM N: A at cols 0..261(+2 pad), B at cols 264..525
#define ABLD 528
#define MGN 914
#define MGLD 916
#define GXN 786
#define GXLD 788

// ---------------- scratch (zero-initialized device globals) ----------------
__device__ float g_h  [NM*DP];     // fp32 h state (pad cols stay 0)
__device__ float g_hq [NM*DP];     // tf32-quantized h (GEMM A operand)
__device__ float g_AB [NM*ABLD];
__device__ float g_Wab[ABN*DP];    // quantized packed [W1a | 0 | W1b | 0]
__device__ float g_bab[ABLD];      // [b1 | 0]
__device__ float g_Wmg[MGN*DP];    // quantized packed [msg_w; gru_w_hh]
__device__ float g_bmg[MGLD];      // [msg_b | gru_b_hh | 0]
__device__ float g_Wih[G3*MSGD];   // quantized gru_w_ih
__device__ float g_mg [NM*MGLD];   // [msg | gh]
__device__ float g_att[NB*MB*MB];
__device__ float g_mv [NM*MSGD];   // quantized
__device__ float g_gx [NM*GXLD];
__device__ float g_w2p[264];       // padded link_w2
__device__ float g_zero[264];      // stays zero

__device__ __forceinline__ float sigmoidf(float x) {
    return 1.0f / (1.0f + expf(-x));
}
__device__ __forceinline__ uint32_t f2tf(float v) {
    uint32_t r; asm("cvt.rna.tf32.f32 %0, %1;" : "=r"(r) : "f"(v)); return r;
}
__device__ __forceinline__ float f2tff(float v) {
    return __uint_as_float(f2tf(v));
}
__device__ __forceinline__ void mma_tf32(float* c, const uint32_t* a, const uint32_t* b) {
    asm volatile(
        "mma.sync.aligned.m16n8k8.row.col.f32.tf32.tf32.f32 "
        "{%0,%1,%2,%3}, {%4,%5,%6,%7}, {%8,%9}, {%0,%1,%2,%3};\n"
        : "+f"(c[0]), "+f"(c[1]), "+f"(c[2]), "+f"(c[3])
        : "r"(a[0]), "r"(a[1]), "r"(a[2]), "r"(a[3]), "r"(b[0]), "r"(b[1]));
}

// ---------------- build h = [feat, pos] (fp32 + quantized copy) ----------------
__global__ void build_nf_kernel(const float* __restrict__ feat,
                                const float* __restrict__ pos) {
    int idx = blockIdx.x * blockDim.x + threadIdx.x;
    if (idx >= NM * DD) return;
    int row = idx / DD, c = idx % DD;
    float v = (c < FEATD) ? feat[row * FEATD + c] : pos[row * POSD + (c - FEATD)];
    g_h [row * DP + c] = v;
    g_hq[row * DP + c] = f2tff(v);
}

// ---------------- pack + pre-quantize weights ----------------
__global__ void pack_kernel(const float* __restrict__ link_w1,
                            const float* __restrict__ link_b1,
                            const float* __restrict__ link_w2,
                            const float* __restrict__ msg_w,
                            const float* __restrict__ msg_b,
                            const float* __restrict__ gru_w_ih,
                            const float* __restrict__ gru_w_hh,
                            const float* __restrict__ gru_b_hh) {
    int idx = blockIdx.x * blockDim.x + threadIdx.x;
    int stride = gridDim.x * blockDim.x;
    // Wab rows: 0..261 = W1a; 264..525 = W1b
    for (int i = idx; i < 524 * DD; i += stride) {
        int n = i / DD, k = i % DD;
        int dr = (n < DD) ? n : (n + 2);
        float v = (n < DD) ? link_w1[n * 524 + k] : link_w1[(n - DD) * 524 + DD + k];
        g_Wab[dr * DP + k] = f2tff(v);
    }
    for (int i = idx; i < MGN * DD; i += stride) {
        int n = i / DD, k = i % DD;
        float v = (n < MSGD) ? msg_w[n * DD + k] : gru_w_hh[(n - MSGD) * DD + k];
        g_Wmg[n * DP + k] = f2tff(v);
    }
    for (int i = idx; i < G3 * MSGD; i += stride) g_Wih[i] = f2tff(gru_w_ih[i]);
    for (int i = idx; i < DD; i += stride) {
        g_bab[i] = link_b1[i];
        g_w2p[i] = link_w2[i];
    }
    for (int i = idx; i < MGN; i += stride)
        g_bmg[i] = (i < MSGD) ? msg_b[i] : gru_b_hh[i - MSGD];
}

// ---------------- TF32 TC GEMM: C = A * W^T + bias ----------------
// A: 2048 x K (lda %4==0, pre-quantized tf32 bits), W: N x K (quantized),
// C: 2048 x N. K % 32 == 0. Block 64x128, 8 warps, warp 32x32 m16n8k8.
// Smem: non-interleaved, SLD=36 -> conflict-free scalar fragment loads.
#define BK 32
#define SLD 36
__global__ __launch_bounds__(256) void gemm_tc_kernel(
        const float* __restrict__ A, int lda,
        const float* __restrict__ W, int ldw,
        const float* __restrict__ bias,
        float* __restrict__ C, int ldc, int N, int K) {
    __shared__ uint32_t As[64 * SLD];
    __shared__ uint32_t Ws[128 * SLD];

    int tid = threadIdx.x;
    int warp = tid >> 5, lane = tid & 31;
    int gid = lane >> 2, tig = lane & 3;
    int wm = (warp >> 2) * 32;
    int wn = (warp & 3) * 32;
    int m0 = blockIdx.y * 64, n0 = blockIdx.x * 128;

    int arow = tid >> 2, akc = (tid & 3) * 8;   // A: 64 rows x 32k, 8 vals/thread
    int wrow = tid >> 1, wkc = (tid & 1) * 16;  // W: 128 rows x 32k, 16 vals/thread
    int wng = n0 + wrow;
    int wclamp = (wng < N) ? wng : (N - 1);
    const uint4* ap = (const uint4*)(A + (size_t)(m0 + arow) * lda + akc);
    const uint4* wp = (const uint4*)(W + (size_t)wclamp * ldw + wkc);

    float acc[2][4][4];
    #pragma unroll
    for (int i = 0; i < 2; i++)
        #pragma unroll
        for (int j = 0; j < 4; j++)
            #pragma unroll
            for (int q = 0; q < 4; q++) acc[i][j][q] = 0.0f;

    int nk = K / BK;
    uint4 va0, va1, vw0, vw1, vw2, vw3;
    va0 = ap[0]; va1 = ap[1];
    vw0 = wp[0]; vw1 = wp[1]; vw2 = wp[2]; vw3 = wp[3];

    for (int it = 0; it < nk; it++) {
        __syncthreads();
        {
            uint32_t* ad = As + arow * SLD + akc;
            *(uint4*)(ad)     = va0;
            *(uint4*)(ad + 4) = va1;
            uint32_t* wd = Ws + wrow * SLD + wkc;
            *(uint4*)(wd)      = vw0;
            *(uint4*)(wd + 4)  = vw1;
            *(uint4*)(wd + 8)  = vw2;
            *(uint4*)(wd + 12) = vw3;
        }
        __syncthreads();

        if (it + 1 < nk) {
            int o = (it + 1) * 8;
            va0 = ap[o]; va1 = ap[o + 1];
            vw0 = wp[o]; vw1 = wp[o + 1]; vw2 = wp[o + 2]; vw3 = wp[o + 3];
        }

        #pragma unroll
        for (int ks = 0; ks < 4; ks++) {
            int kb = ks * 8;
            uint32_t af[2][4], bf[4][2];
            #pragma unroll
            for (int mf = 0; mf < 2; mf++) {
                const uint32_t* pa = As + (wm + mf * 16 + gid) * SLD + kb + tig;
                af[mf][0] = pa[0];
                af[mf][1] = pa[8 * SLD];
                af[mf][2] = pa[4];
                af[mf][3] = pa[8 * SLD + 4];
            }
            #pragma unroll
            for (int nf = 0; nf < 4; nf++) {
                const uint32_t* pb = Ws + (wn + nf * 8 + gid) * SLD + kb + tig;
                bf[nf][0] = pb[0];
                bf[nf][1] = pb[4];
            }
            #pragma unroll
            for (int mf = 0; mf < 2; mf++)
                #pragma unroll
                for (int nf = 0; nf < 4; nf++)
                    mma_tf32(acc[mf][nf], af[mf], bf[nf]);
        }
    }

    #pragma unroll
    for (int nf = 0; nf < 4; nf++) {
        int col = n0 + wn + nf * 8 + tig * 2;
        if (col >= N) continue;
        float2 bv = *(const float2*)(bias + col);
        #pragma unroll
        for (int mf = 0; mf < 2; mf++) {
            int r0 = m0 + wm + mf * 16 + gid;
            float2 v0 = make_float2(acc[mf][nf][0] + bv.x, acc[mf][nf][1] + bv.y);
            float2 v1 = make_float2(acc[mf][nf][2] + bv.x, acc[mf][nf][3] + bv.y);
            *(float2*)(C + (size_t)r0 * ldc + col) = v0;
            *(float2*)(C + (size_t)(r0 + 8) * ldc + col) = v1;
        }
    }
}

// ---------------- attention: warp per (b,n,w) pair, float4 loads ----------------
__global__ void att_kernel(const float* __restrict__ b2v,
                           const int* __restrict__ num_rec,
                           float* __restrict__ att_out) {
    int gw = (blockIdx.x * blockDim.x + threadIdx.x) >> 5;
    int lane = threadIdx.x & 31;
    if (gw >= NB * MB * MB) return;
    int b = gw >> 10, n = (gw >> 5) & 31, w = gw & 31;
    int nr = num_rec[b];
    bool valid = (n < nr) && (w < nr);

    const float4* ra = valid ? (const float4*)(g_AB + (size_t)(b * MB + n) * ABLD)
                             : (const float4*)g_bab;        // [b1 | 0]
    const float4* rb = valid ? (const float4*)(g_AB + (size_t)(b * MB + w) * ABLD + 264)
                             : (const float4*)g_zero;
    const float4* wv = (const float4*)g_w2p;

    float s = 0.0f;
    #pragma unroll 1
    for (int i = lane; i < 66; i += 32) {        // 264 floats (pad w2=0)
        float4 a = ra[i], bb = rb[i], ww = wv[i];
        s = fmaf(fmaxf(a.x + bb.x, 0.0f), ww.x, s);
        s = fmaf(fmaxf(a.y + bb.y, 0.0f), ww.y, s);
        s = fmaf(fmaxf(a.z + bb.z, 0.0f), ww.z, s);
        s = fmaf(fmaxf(a.w + bb.w, 0.0f), ww.w, s);
    }
    #pragma unroll
    for (int o = 16; o > 0; o >>= 1) s += __shfl_xor_sync(0xffffffffu, s, o);
    if (lane == 0) {
        float a = sigmoidf(s + b2v[0]);
        g_att[gw] = a;
        att_out[gw] = a;
    }
}

// ---------------- mv[b,n,k] = sum_{w<nr} att[b,n,w] * msg[b,w,k] (quantized out) ----------------
__global__ void mv_kernel(const int* __restrict__ num_rec) {
    int bn = blockIdx.x;
    int b = bn >> 5;
    int k = threadIdx.x;              // 0..127
    int nr = num_rec[b];
    const float* arow = g_att + (size_t)bn * MB;
    const float* mb = g_mg + (size_t)b * MB * MGLD;
    float s = 0.0f;
    for (int w = 0; w < nr; w++) s = fmaf(arow[w], mb[(size_t)w * MGLD + k], s);
    g_mv[(size_t)bn * MSGD + k] = f2tff(s);
}

// ---------------- GRU combine: h (fp32 + quantized), vmask, float2 ----------------
__global__ void gru_kernel(const int* __restrict__ num_rec) {
    int idx = blockIdx.x * blockDim.x + threadIdx.x;
    if (idx >= NM * 131) return;
    int row = idx / 131, d = (idx % 131) * 2;
    int b = row >> 5, m = row & 31;
    const float* gx = g_gx + (size_t)row * GXLD + d;
    const float* gh = g_mg + (size_t)row * MGLD + MSGD + d;
    float2 xr = *(const float2*)(gx);
    float2 xz = *(const float2*)(gx + 262);
    float2 xn = *(const float2*)(gx + 524);
    float2 hr = *(const float2*)(gh);
    float2 hz = *(const float2*)(gh + 262);
    float2 hn = *(const float2*)(gh + 524);
    float2 hv = *(const float2*)(g_h + (size_t)row * DP + d);
    float rx = sigmoidf(xr.x + hr.x), ry = sigmoidf(xr.y + hr.y);
    float zx = sigmoidf(xz.x + hz.x), zy = sigmoidf(xz.y + hz.y);
    float cx = tanhf(xn.x + rx * hn.x), cy = tanhf(xn.y + ry * hn.y);
    float ox = (1.0f - zx) * cx + zx * hv.x;
    float oy = (1.0f - zy) * cy + zy * hv.y;
    bool live = (m < num_rec[b]);
    ox = live ? ox : 0.0f;
    oy = live ? oy : 0.0f;
    *(float2*)(g_h  + (size_t)row * DP + d) = make_float2(ox, oy);
    *(float2*)(g_hq + (size_t)row * DP + d) = make_float2(f2tff(ox), f2tff(oy));
}

// ---------------- fused readout ----------------
#define SH_LD 266
#define ST_LD 133
__global__ void readout_kernel(const float* __restrict__ ro_w1,
                               const float* __restrict__ ro_b1,
                               const float* __restrict__ ro_w2,
                               const float* __restrict__ ro_b2,
                               const int* __restrict__ num_rec,
                               float* __restrict__ out) {
    extern __shared__ float s[];
    float* sh = s;                    // 32 x 266
    float* st = s + MB * SH_LD;       // 32 x 133
    int b = blockIdx.x;
    int tid = threadIdx.x;            // 0..511
    int lane = tid & 31, wid = tid >> 5;

    for (int i = tid; i < MB * 131; i += 512) {
        int r = i / 131, d = (i % 131) * 2;
        *(float2*)(sh + r * SH_LD + d) = *(const float2*)(g_h + (size_t)(b * MB + r) * DP + d);
    }
    __syncthreads();

    int r = lane;
    #pragma unroll 1
    for (int j = 0; j < 8; j++) {
        int k = wid * 8 + j;
        const float2* wrow = (const float2*)(ro_w1 + (size_t)k * DD);
        const float2* hrow = (const float2*)(sh + r * SH_LD);
        float acc = 0.0f;
        #pragma unroll 4
        for (int i = 0; i < DD / 2; i++) {
            float2 ww = __ldg(wrow + i);
            float2 hh = hrow[i];
            acc = fmaf(hh.x, ww.x, acc);
            acc = fmaf(hh.y, ww.y, acc);
        }
        st[r * ST_LD + k] = fmaxf(acc + ro_b1[k], 0.0f);
    }
    __syncthreads();

    if (tid < MB * NCLSD) {
        int rr = tid / NCLSD, c = tid % NCLSD;
        int nr = num_rec[b];
        float acc = ro_b2[c];
        #pragma unroll 4
        for (int k = 0; k < MSGD; k++)
            acc = fmaf(st[rr * ST_LD + k], __ldg(ro_w2 + (size_t)c * MSGD + k), acc);
        out[(size_t)(b * MB + rr) * NCLSD + c] = (rr < nr) ? acc : 0.0f;
    }
}

// ---------------- host launcher ----------------
static void launch_gemm(const float* A, int lda, const float* W, int ldw,
                        const float* bias, float* C, int ldc, int N, int K) {
    dim3 grid((N + 127) / 128, NM / 64);
    gemm_tc_kernel<<<grid, 256>>>(A, lda, W, ldw, bias, C, ldc, N, K);
}

extern "C" void kernel_launch(void* const* d_in, const int* in_sizes, int n_in,
                              void* d_out, int out_size) {
    const float* feat    = (const float*)d_in[0];
    const float* pos     = (const float*)d_in[1];
    const int*   num_rec = (const int*)  d_in[2];
    const float* link_w1 = (const float*)d_in[3];
    const float* link_b1 = (const float*)d_in[4];
    const float* link_w2 = (const float*)d_in[5];
    const float* link_b2 = (const float*)d_in[6];
    const float* msg_w   = (const float*)d_in[7];
    const float* msg_b   = (const float*)d_in[8];
    const float* gru_w_ih= (const float*)d_in[9];
    const float* gru_w_hh= (const float*)d_in[10];
    const float* gru_b_ih= (const float*)d_in[11];
    const float* gru_b_hh= (const float*)d_in[12];
    const float* ro_w1   = (const float*)d_in[13];
    const float* ro_b1   = (const float*)d_in[14];
    const float* ro_w2   = (const float*)d_in[15];
    const float* ro_b2   = (const float*)d_in[16];
    float* out = (float*)d_out;           // [pred (64*32*7) | attmat (64*32*32)]

    float *p_h, *p_hq, *p_AB, *p_Wab, *p_bab, *p_Wmg, *p_bmg, *p_Wih, *p_mg, *p_mv, *p_gx;
    cudaGetSymbolAddress((void**)&p_h,   g_h);
    cudaGetSymbolAddress((void**)&p_hq,  g_hq);
    cudaGetSymbolAddress((void**)&p_AB,  g_AB);
    cudaGetSymbolAddress((void**)&p_Wab, g_Wab);
    cudaGetSymbolAddress((void**)&p_bab, g_bab);
    cudaGetSymbolAddress((void**)&p_Wmg, g_Wmg);
    cudaGetSymbolAddress((void**)&p_bmg, g_bmg);
    cudaGetSymbolAddress((void**)&p_Wih, g_Wih);
    cudaGetSymbolAddress((void**)&p_mg,  g_mg);
    cudaGetSymbolAddress((void**)&p_mv,  g_mv);
    cudaGetSymbolAddress((void**)&p_gx,  g_gx);

    static const size_t RO_SMEM = (size_t)(MB * SH_LD + MB * ST_LD) * sizeof(float);
    cudaFuncSetAttribute(readout_kernel, cudaFuncAttributeMaxDynamicSharedMemorySize,
                         (int)RO_SMEM);

    // 1) h = [feat, pos] (+ quantized twin); pack + quantize weights
    build_nf_kernel<<<(NM * DD + 255) / 256, 256>>>(feat, pos);
    pack_kernel<<<296, 256>>>(link_w1, link_b1, link_w2, msg_w, msg_b,
                              gru_w_ih, gru_w_hh, gru_b_hh);

    // 2) edge MLP low-rank: AB = hq @ Wab^T + [b1|0]   (2048 x 528)
    launch_gemm(p_hq, DP, p_Wab, DP, p_bab, p_AB, ABLD, ABN, DP);

    // 3) attention
    {
        int threads = NB * MB * MB * 32;
        att_kernel<<<(threads + 255) / 256, 256>>>(link_b2, num_rec, out + NM * NCLSD);
    }

    // 4) two message-passing GRU rounds
    for (int round = 0; round < 2; round++) {
        launch_gemm(p_hq, DP, p_Wmg, DP, p_bmg, p_mg, MGLD, MGN, DP);    // [msg|gh]
        mv_kernel<<<NM, MSGD>>>(num_rec);
        launch_gemm(p_mv, MSGD, p_Wih, MSGD, gru_b_ih, p_gx, GXLD, GXN, MSGD);
        gru_kernel<<<(NM * 131 + 255) / 256, 256>>>(num_rec);
    }

    // 5) fused readout
    readout_kernel<<<NB, 512, RO_SMEM>>>(ro_w1, ro_b1, ro_w2, ro_b2, num_rec, out);

    (void)in_sizes; (void)n_in; (void)out_size;
}